// round 13
// baseline (speedup 1.0000x reference)
#include <cuda_runtime.h>

#define B_ 16
#define N_ 4096
#define D_ 64
#define S_ 1024
#define K_ 32

__device__ int g_fps_idx[B_ * S_];
__device__ float g_xyz_soa[B_ * 3 * N_];  // SoA xyz, written by fps_kernel
__device__ float g_P1[B_ * N_ * 64];      // b1f + points @ W1f[3:67]

typedef unsigned long long u64t;

__device__ __forceinline__ u64t pack2(float x, float y) {
    u64t r; asm("mov.b64 %0,{%1,%2};" : "=l"(r) : "f"(x), "f"(y)); return r;
}
__device__ __forceinline__ void unpack2(u64t v, float& x, float& y) {
    asm("mov.b64 {%0,%1},%2;" : "=f"(x), "=f"(y) : "l"(v));
}
__device__ __forceinline__ void ffma2(u64t& d, u64t a, u64t b) {
    asm("fma.rn.f32x2 %0,%1,%2,%0;" : "+l"(d) : "l"(a), "l"(b));
}
__device__ __forceinline__ u64t add2(u64t a, u64t b) {
    u64t r; asm("add.rn.f32x2 %0,%1,%2;" : "=l"(r) : "l"(a), "l"(b)); return r;
}
__device__ __forceinline__ u64t sqr2(u64t a) {
    u64t r; asm("mul.rn.f32x2 %0,%1,%1;" : "=l"(r) : "l"(a)); return r;
}
__device__ __forceinline__ u64t fmasq2(u64t a, u64t c) {   // a*a + c
    u64t r; asm("fma.rn.f32x2 %0,%1,%1,%2;" : "=l"(r) : "l"(a), "l"(c)); return r;
}
__device__ __forceinline__ unsigned redux_max(unsigned v) {
    unsigned r;
    asm("redux.sync.max.u32 %0, %1, 0xffffffff;" : "=r"(r) : "r"(v));
    return r;
}

// ---------------------------------------------------------------------------
// Kernel 1: farthest point sampling. 512 thr, 8 pts/thr held as 4 f32x2 pairs.
// Distance math packed (bit-exact per element: sub = add of negation, same
// fma chain). Argmax tail: REDUX + ballot (R10-proven). Also dumps SoA xyz.
// ---------------------------------------------------------------------------
__global__ __launch_bounds__(512) void fps_kernel(const float* __restrict__ xyz,
                                                  float* __restrict__ out_xyz) {
    extern __shared__ float sm[];
    float* xs = sm;
    float* ys = sm + N_;
    float* zs = sm + 2 * N_;
    __shared__ unsigned s_val[2][16];
    __shared__ int      s_idx[2][16];

    const int b = blockIdx.x, t = threadIdx.x;
    const int warp = t >> 5, lane = t & 31;
    const float* src = xyz + (size_t)b * N_ * 3;
    for (int i = t; i < N_; i += 512) {
        xs[i] = src[3 * i + 0];
        ys[i] = src[3 * i + 1];
        zs[i] = src[3 * i + 2];
    }
    __syncthreads();
    // SoA dump for sa_kernel (coalesced)
    float* soa = g_xyz_soa + (size_t)b * 3 * N_;
    for (int i = t; i < N_; i += 512) {
        soa[i]          = xs[i];
        soa[N_ + i]     = ys[i];
        soa[2 * N_ + i] = zs[i];
    }

    u64t px2[4], py2[4], pz2[4];
    float md[8];
#pragma unroll
    for (int j = 0; j < 4; j++) {
        int p = t * 8 + 2 * j;
        px2[j] = pack2(xs[p], xs[p + 1]);
        py2[j] = pack2(ys[p], ys[p + 1]);
        pz2[j] = pack2(zs[p], zs[p + 1]);
        md[2 * j] = 1e10f; md[2 * j + 1] = 1e10f;
    }

    int last = 0;
#pragma unroll 1
    for (int it = 0; it < S_; ++it) {
        if (t == 0) {
            g_fps_idx[b * S_ + it] = last;
            float* o = out_xyz + ((size_t)b * S_ + it) * 3;
            o[0] = xs[last]; o[1] = ys[last]; o[2] = zs[last];
        }
        const float cx = xs[last], cy = ys[last], cz = zs[last];
        const u64t ncx = pack2(-cx, -cx), ncy = pack2(-cy, -cy),
                   ncz = pack2(-cz, -cz);
        float bv = -1.0f;
#pragma unroll
        for (int j = 0; j < 4; j++) {
            u64t dx = add2(px2[j], ncx);
            u64t dy = add2(py2[j], ncy);
            u64t dz = add2(pz2[j], ncz);
            u64t dd = fmasq2(dx, fmasq2(dy, sqr2(dz)));
            float dlo, dhi;
            unpack2(dd, dlo, dhi);
            float m0 = fminf(md[2 * j + 0], dlo);
            float m1 = fminf(md[2 * j + 1], dhi);
            md[2 * j + 0] = m0;
            md[2 * j + 1] = m1;
            bv = fmaxf(bv, fmaxf(m0, m1));
        }
        int bj = 7;
#pragma unroll
        for (int j = 7; j >= 0; j--) if (md[j] == bv) bj = j;   // lowest local j
        const int bi = t * 8 + bj;
        const unsigned bb = __float_as_uint(bv);
        const unsigned wv = redux_max(bb);
        const unsigned msk = __ballot_sync(0xffffffffu, bb == wv);
        const int srcl = __ffs(msk) - 1;
        const int wbi = __shfl_sync(0xffffffffu, bi, srcl);
        const int buf = it & 1;
        if (lane == 0) { s_val[buf][warp] = wv; s_idx[buf][warp] = wbi; }
        __syncthreads();
        const unsigned v = s_val[buf][lane & 15];
        const unsigned w2 = redux_max(v);
        const unsigned m2 = __ballot_sync(0xffffffffu, v == w2);
        const int k = __ffs(m2) - 1;
        last = s_idx[buf][k];
    }
}

// ---------------------------------------------------------------------------
// Packed f32x2 helpers.
// ---------------------------------------------------------------------------
__device__ __forceinline__ void acc_fma64p(u64t* acc, const float* w, u64t xx) {
#pragma unroll
    for (int i = 0; i < 16; i++) {
        ulonglong2 wv = *reinterpret_cast<const ulonglong2*>(w + 4 * i);
        ffma2(acc[2 * i + 0], wv.x, xx);
        ffma2(acc[2 * i + 1], wv.y, xx);
    }
}
__device__ __forceinline__ void acc_fma32p(u64t* acc, const float* w, u64t xx) {
#pragma unroll
    for (int i = 0; i < 8; i++) {
        ulonglong2 wv = *reinterpret_cast<const ulonglong2*>(w + 4 * i);
        ffma2(acc[2 * i + 0], wv.x, xx);
        ffma2(acc[2 * i + 1], wv.y, xx);
    }
}
__device__ __forceinline__ void load64p(u64t* dst, const float* src) {
#pragma unroll
    for (int i = 0; i < 16; i++) {
        ulonglong2 t = *reinterpret_cast<const ulonglong2*>(src + 4 * i);
        dst[2 * i + 0] = t.x;
        dst[2 * i + 1] = t.y;
    }
}
__device__ __forceinline__ void load32p(u64t* dst, const float* src) {
#pragma unroll
    for (int i = 0; i < 8; i++) {
        ulonglong2 t = *reinterpret_cast<const ulonglong2*>(src + 4 * i);
        dst[2 * i + 0] = t.x;
        dst[2 * i + 1] = t.y;
    }
}

// ---------------------------------------------------------------------------
// Kernel 1b: precompute P1[b][n][:] = b1f + points[b,n,:] @ W1f[3:67,:].
// ---------------------------------------------------------------------------
__global__ __launch_bounds__(256) void pre_kernel(
    const float* __restrict__ points,
    const float* __restrict__ W0, const float* __restrict__ b0,
    const float* __restrict__ g0, const float* __restrict__ be0,
    const float* __restrict__ m0, const float* __restrict__ v0) {
    __shared__ float Wf[64 * 64];
    __shared__ float bf[64];

    const int b = blockIdx.y, tid = threadIdx.x;
    for (int i = tid; i < 64 * 64; i += 256) {
        int d = i & 63;
        Wf[i] = W0[(3 * 64) + i] * (g0[d] * rsqrtf(v0[d] + 1e-5f));
    }
    if (tid < 64) {
        float s = g0[tid] * rsqrtf(v0[tid] + 1e-5f);
        bf[tid] = (b0[tid] - m0[tid]) * s + be0[tid];
    }
    __syncthreads();

    const int row = blockIdx.x * 256 + tid;
    const float4* prow =
        reinterpret_cast<const float4*>(points + ((size_t)b * N_ + row) * D_);
    u64t acc[32];
    load64p(acc, bf);
#pragma unroll
    for (int j = 0; j < 16; j++) {
        float4 p = prow[j];
        acc_fma64p(acc, Wf + (4 * j + 0) * 64, pack2(p.x, p.x));
        acc_fma64p(acc, Wf + (4 * j + 1) * 64, pack2(p.y, p.y));
        acc_fma64p(acc, Wf + (4 * j + 2) * 64, pack2(p.z, p.z));
        acc_fma64p(acc, Wf + (4 * j + 3) * 64, pack2(p.w, p.w));
    }
    ulonglong2* out = reinterpret_cast<ulonglong2*>(
        g_P1 + ((size_t)b * N_ + row) * 64);
#pragma unroll
    for (int i = 0; i < 16; i++) {
        ulonglong2 t;
        t.x = acc[2 * i + 0];
        t.y = acc[2 * i + 1];
        out[i] = t;
    }
}

// Shared layout (floats), weights only (xyz via g_xyz_soa / L1):
//  0 W1x[3*64]; 192 W2f[64*64]; 4288 b2f[64]; 4352 W3f[64*128];
//  12544 b3f[128]; 12672 grp[5*32] (int) -> 12832 floats = 51328 bytes
#define SMEM_B_BYTES (12832 * 4)
#define NBX 18
#define SPB 57    // 18*57 = 1026 >= 1024

// ---------------------------------------------------------------------------
// Kernel 2: ball query + P1 gather + xyz-layer1 + MLP + max-pool.
// 160 threads (5 warps), grid (18,16) = 288 CTAs -> 2 CTAs/SM, 10 warps/SM.
// No launch_bounds reg cap (65536/160 = 409) -> ptxas free, no spill.
// ---------------------------------------------------------------------------
__global__ __launch_bounds__(160) void sa_kernel(
    const float* __restrict__ W0,
    const float* __restrict__ g0, const float* __restrict__ v0,
    const float* __restrict__ W1, const float* __restrict__ b1,
    const float* __restrict__ g1, const float* __restrict__ be1,
    const float* __restrict__ m1, const float* __restrict__ v1,
    const float* __restrict__ W2, const float* __restrict__ b2,
    const float* __restrict__ g2, const float* __restrict__ be2,
    const float* __restrict__ m2, const float* __restrict__ v2,
    float* __restrict__ out_pts) {
    extern __shared__ float sm[];
    float* W1x = sm;
    float* W2f = sm + 192;
    float* b2f = sm + 4288;
    float* W3f = sm + 4352;
    float* b3f = sm + 12544;
    int* grpAll = (int*)(sm + 12672);

    const int b = blockIdx.y, tid = threadIdx.x;
    const float* xs = g_xyz_soa + (size_t)b * 3 * N_;
    const float* ys = xs + N_;
    const float* zs = xs + 2 * N_;

    for (int i = tid; i < 3 * 64; i += 160) {
        int d = i & 63;
        W1x[i] = W0[i] * (g0[d] * rsqrtf(v0[d] + 1e-5f));
    }
    for (int i = tid; i < 64 * 64; i += 160) {
        int d = i & 63;
        W2f[i] = W1[i] * (g1[d] * rsqrtf(v1[d] + 1e-5f));
    }
    for (int i = tid; i < 64 * 128; i += 160) {
        int d = i & 127;
        W3f[i] = W2[i] * (g2[d] * rsqrtf(v2[d] + 1e-5f));
    }
    if (tid < 64) {
        float s = g1[tid] * rsqrtf(v1[tid] + 1e-5f);
        b2f[tid] = (b1[tid] - m1[tid]) * s + be1[tid];
    }
    if (tid < 128) {
        float s = g2[tid] * rsqrtf(v2[tid] + 1e-5f);
        b3f[tid] = (b2[tid] - m2[tid]) * s + be2[tid];
    }
    __syncthreads();

    const int w = tid >> 5, lane = tid & 31;
    int* grp = grpAll + w * K_;

    const int s0   = blockIdx.x * SPB;
    const int send = min(s0 + SPB, S_);

#pragma unroll 1
    for (int s = s0 + w; s < send; s += 5) {
        const int fidx = g_fps_idx[b * S_ + s];
        const float cx = __ldg(xs + fidx), cy = __ldg(ys + fidx),
                    cz = __ldg(zs + fidx);

        // ---- ball query: first-K in index order, ballot+popc, early exit ----
        grp[lane] = -1;
        __syncwarp();
        int cnt = 0;
        for (int base = 0; base < N_ && cnt < K_; base += 32) {
            const int j = base + lane;
            float dx = __ldg(xs + j) - cx, dy = __ldg(ys + j) - cy,
                  dz = __ldg(zs + j) - cz;
            float d2 = dx * dx + dy * dy + dz * dz;
            bool hit = d2 < 0.04f;   // f32(0.2**2), matches jax weak-typing
            unsigned mask = __ballot_sync(0xffffffffu, hit);
            if (hit) {
                int pos = cnt + __popc(mask & ((1u << lane) - 1u));
                if (pos < K_) grp[pos] = j;
            }
            cnt += __popc(mask);
        }
        __syncwarp();
        const int ni = grp[lane];
        const bool valid = ni >= 0;
        const int pidx = valid ? ni : (N_ - 1);          // torch -1 wrap
        const float in0 = (valid ? __ldg(xs + ni) : 0.0f) - cx;
        const float in1 = (valid ? __ldg(ys + ni) : 0.0f) - cy;
        const float in2 = (valid ? __ldg(zs + ni) : 0.0f) - cz;
        const ulonglong2* p1row = reinterpret_cast<const ulonglong2*>(
            g_P1 + ((size_t)b * N_ + pidx) * 64);

        // ---- layer 1: acc = P1row + xyz-only inputs ----
        u64t hp[32];
#pragma unroll
        for (int i = 0; i < 16; i++) {
            ulonglong2 t = p1row[i];
            hp[2 * i + 0] = t.x;
            hp[2 * i + 1] = t.y;
        }
        acc_fma64p(hp, W1x + 0 * 64, pack2(in0, in0));
        acc_fma64p(hp, W1x + 1 * 64, pack2(in1, in1));
        acc_fma64p(hp, W1x + 2 * 64, pack2(in2, in2));
        float h[64];
#pragma unroll
        for (int i = 0; i < 32; i++) {
            float a, c2;
            unpack2(hp[i], a, c2);
            h[2 * i + 0] = fmaxf(a, 0.0f);
            h[2 * i + 1] = fmaxf(c2, 0.0f);
        }

        // ---- layer 2: 64 -> 64 ----
        u64t h2p[32];
        load64p(h2p, b2f);
#pragma unroll
        for (int c = 0; c < 64; c++) acc_fma64p(h2p, W2f + c * 64, pack2(h[c], h[c]));
        float h2[64];
#pragma unroll
        for (int i = 0; i < 32; i++) {
            float a, c2;
            unpack2(h2p[i], a, c2);
            h2[2 * i + 0] = fmaxf(a, 0.0f);
            h2[2 * i + 1] = fmaxf(c2, 0.0f);
        }

        // ---- layer 3: 64 -> 128 in 4 chunks of 32, fused max over K ----
        float* outp = out_pts + ((size_t)(b * S_ + s)) * 128;
#pragma unroll 1
        for (int q = 0; q < 4; q++) {
            u64t vp[16];
            load32p(vp, b3f + q * 32);
#pragma unroll
            for (int c = 0; c < 64; c++)
                acc_fma32p(vp, W3f + c * 128 + q * 32, pack2(h2[c], h2[c]));
            float v[32];
#pragma unroll
            for (int i = 0; i < 16; i++) {
                float a, c2;
                unpack2(vp[i], a, c2);
                v[2 * i + 0] = fmaxf(a, 0.0f);
                v[2 * i + 1] = fmaxf(c2, 0.0f);
            }
            // transpose-reduce: lane l ends with max over lanes of ch q*32+l
#pragma unroll
            for (int hh = 16; hh >= 1; hh >>= 1) {
#pragma unroll
                for (int i = 0; i < hh; i++) {
                    float send2 = (lane & hh) ? v[i] : v[i + hh];
                    float recv = __shfl_xor_sync(0xffffffffu, send2, hh);
                    float keep = (lane & hh) ? v[i + hh] : v[i];
                    v[i] = fmaxf(keep, recv);
                }
            }
            outp[q * 32 + lane] = v[0];
        }
    }
}

// ---------------------------------------------------------------------------
extern "C" void kernel_launch(void* const* d_in, const int* in_sizes, int n_in,
                              void* d_out, int out_size) {
    const float* xyz    = (const float*)d_in[0];
    const float* points = (const float*)d_in[1];
    const float* W0  = (const float*)d_in[2];
    const float* b0  = (const float*)d_in[3];
    const float* g0  = (const float*)d_in[4];
    const float* be0 = (const float*)d_in[5];
    const float* m0  = (const float*)d_in[6];
    const float* v0  = (const float*)d_in[7];
    const float* W1  = (const float*)d_in[8];
    const float* b1  = (const float*)d_in[9];
    const float* g1  = (const float*)d_in[10];
    const float* be1 = (const float*)d_in[11];
    const float* m1  = (const float*)d_in[12];
    const float* v1  = (const float*)d_in[13];
    const float* W2  = (const float*)d_in[14];
    const float* b2  = (const float*)d_in[15];
    const float* g2  = (const float*)d_in[16];
    const float* be2 = (const float*)d_in[17];
    const float* m2  = (const float*)d_in[18];
    const float* v2  = (const float*)d_in[19];

    float* out_xyz = (float*)d_out;                       // (B,S,3)
    float* out_pts = (float*)d_out + (size_t)B_ * S_ * 3; // (B,S,128)

    cudaFuncSetAttribute(fps_kernel, cudaFuncAttributeMaxDynamicSharedMemorySize,
                         3 * N_ * 4);
    cudaFuncSetAttribute(sa_kernel, cudaFuncAttributeMaxDynamicSharedMemorySize,
                         SMEM_B_BYTES);

    fps_kernel<<<B_, 512, 3 * N_ * 4>>>(xyz, out_xyz);
    pre_kernel<<<dim3(16, B_), 256>>>(points, W0, b0, g0, be0, m0, v0);
    sa_kernel<<<dim3(NBX, B_), 160, SMEM_B_BYTES>>>(
        W0, g0, v0,
        W1, b1, g1, be1, m1, v1,
        W2, b2, g2, be2, m2, v2,
        out_pts);
}

// round 15
// speedup vs baseline: 1.3219x; 1.3219x over previous
#include <cuda_runtime.h>

#define B_ 16
#define N_ 4096
#define D_ 64
#define S_ 1024
#define K_ 32

__device__ int g_fps_idx[B_ * S_];
__device__ float g_P1[B_ * N_ * 64];   // precomputed b1f + points @ W1f[3:67]

typedef unsigned long long u64t;

__device__ __forceinline__ u64t pack2(float x, float y) {
    u64t r; asm("mov.b64 %0,{%1,%2};" : "=l"(r) : "f"(x), "f"(y)); return r;
}
__device__ __forceinline__ void unpack2(u64t v, float& x, float& y) {
    asm("mov.b64 {%0,%1},%2;" : "=f"(x), "=f"(y) : "l"(v));
}
__device__ __forceinline__ void ffma2(u64t& d, u64t a, u64t b) {
    asm("fma.rn.f32x2 %0,%1,%2,%0;" : "+l"(d) : "l"(a), "l"(b));
}
__device__ __forceinline__ u64t add2(u64t a, u64t b) {
    u64t r; asm("add.rn.f32x2 %0,%1,%2;" : "=l"(r) : "l"(a), "l"(b)); return r;
}
__device__ __forceinline__ u64t sqr2(u64t a) {
    u64t r; asm("mul.rn.f32x2 %0,%1,%1;" : "=l"(r) : "l"(a)); return r;
}
__device__ __forceinline__ u64t fmasq2(u64t a, u64t c) {   // a*a + c
    u64t r; asm("fma.rn.f32x2 %0,%1,%1,%2;" : "=l"(r) : "l"(a), "l"(c)); return r;
}
__device__ __forceinline__ unsigned redux_max(unsigned v) {
    unsigned r;
    asm("redux.sync.max.u32 %0, %1, 0xffffffff;" : "=r"(r) : "r"(v));
    return r;
}

// ---------------------------------------------------------------------------
// Kernel 1: farthest point sampling (R13-proven 416us). 512 thr, 8 pts/thr
// as 4 f32x2 pairs; packed distance math (bit-exact per element); REDUX +
// ballot argmax tail.
// ---------------------------------------------------------------------------
__global__ __launch_bounds__(512) void fps_kernel(const float* __restrict__ xyz,
                                                  float* __restrict__ out_xyz) {
    extern __shared__ float sm[];
    float* xs = sm;
    float* ys = sm + N_;
    float* zs = sm + 2 * N_;
    __shared__ unsigned s_val[2][16];
    __shared__ int      s_idx[2][16];

    const int b = blockIdx.x, t = threadIdx.x;
    const int warp = t >> 5, lane = t & 31;
    const float* src = xyz + (size_t)b * N_ * 3;
    for (int i = t; i < N_; i += 512) {
        xs[i] = src[3 * i + 0];
        ys[i] = src[3 * i + 1];
        zs[i] = src[3 * i + 2];
    }
    __syncthreads();

    u64t px2[4], py2[4], pz2[4];
    float md[8];
#pragma unroll
    for (int j = 0; j < 4; j++) {
        int p = t * 8 + 2 * j;
        px2[j] = pack2(xs[p], xs[p + 1]);
        py2[j] = pack2(ys[p], ys[p + 1]);
        pz2[j] = pack2(zs[p], zs[p + 1]);
        md[2 * j] = 1e10f; md[2 * j + 1] = 1e10f;
    }

    int last = 0;
#pragma unroll 1
    for (int it = 0; it < S_; ++it) {
        if (t == 0) {
            g_fps_idx[b * S_ + it] = last;
            float* o = out_xyz + ((size_t)b * S_ + it) * 3;
            o[0] = xs[last]; o[1] = ys[last]; o[2] = zs[last];
        }
        const float cx = xs[last], cy = ys[last], cz = zs[last];
        const u64t ncx = pack2(-cx, -cx), ncy = pack2(-cy, -cy),
                   ncz = pack2(-cz, -cz);
        float bv = -1.0f;
#pragma unroll
        for (int j = 0; j < 4; j++) {
            u64t dx = add2(px2[j], ncx);
            u64t dy = add2(py2[j], ncy);
            u64t dz = add2(pz2[j], ncz);
            u64t dd = fmasq2(dx, fmasq2(dy, sqr2(dz)));
            float dlo, dhi;
            unpack2(dd, dlo, dhi);
            float m0 = fminf(md[2 * j + 0], dlo);
            float m1 = fminf(md[2 * j + 1], dhi);
            md[2 * j + 0] = m0;
            md[2 * j + 1] = m1;
            bv = fmaxf(bv, fmaxf(m0, m1));
        }
        int bj = 7;
#pragma unroll
        for (int j = 7; j >= 0; j--) if (md[j] == bv) bj = j;   // lowest local j
        const int bi = t * 8 + bj;
        const unsigned bb = __float_as_uint(bv);
        const unsigned wv = redux_max(bb);
        const unsigned msk = __ballot_sync(0xffffffffu, bb == wv);
        const int srcl = __ffs(msk) - 1;
        const int wbi = __shfl_sync(0xffffffffu, bi, srcl);
        const int buf = it & 1;
        if (lane == 0) { s_val[buf][warp] = wv; s_idx[buf][warp] = wbi; }
        __syncthreads();
        const unsigned v = s_val[buf][lane & 15];
        const unsigned w2 = redux_max(v);
        const unsigned m2 = __ballot_sync(0xffffffffu, v == w2);
        const int k = __ffs(m2) - 1;
        last = s_idx[buf][k];
    }
}

// ---------------------------------------------------------------------------
// Packed f32x2 helpers.
// ---------------------------------------------------------------------------
__device__ __forceinline__ void acc_fma64p(u64t* acc, const float* w, u64t xx) {
#pragma unroll
    for (int i = 0; i < 16; i++) {
        ulonglong2 wv = *reinterpret_cast<const ulonglong2*>(w + 4 * i);
        ffma2(acc[2 * i + 0], wv.x, xx);
        ffma2(acc[2 * i + 1], wv.y, xx);
    }
}
__device__ __forceinline__ void acc_fma32p(u64t* acc, const float* w, u64t xx) {
#pragma unroll
    for (int i = 0; i < 8; i++) {
        ulonglong2 wv = *reinterpret_cast<const ulonglong2*>(w + 4 * i);
        ffma2(acc[2 * i + 0], wv.x, xx);
        ffma2(acc[2 * i + 1], wv.y, xx);
    }
}
__device__ __forceinline__ void load64p(u64t* dst, const float* src) {
#pragma unroll
    for (int i = 0; i < 16; i++) {
        ulonglong2 t = *reinterpret_cast<const ulonglong2*>(src + 4 * i);
        dst[2 * i + 0] = t.x;
        dst[2 * i + 1] = t.y;
    }
}
__device__ __forceinline__ void load32p(u64t* dst, const float* src) {
#pragma unroll
    for (int i = 0; i < 8; i++) {
        ulonglong2 t = *reinterpret_cast<const ulonglong2*>(src + 4 * i);
        dst[2 * i + 0] = t.x;
        dst[2 * i + 1] = t.y;
    }
}

// ---------------------------------------------------------------------------
// Kernel 1b: precompute P1[b][n][:] = b1f + points[b,n,:] @ W1f[3:67,:].
// (R12-proven.)
// ---------------------------------------------------------------------------
__global__ __launch_bounds__(256) void pre_kernel(
    const float* __restrict__ points,
    const float* __restrict__ W0, const float* __restrict__ b0,
    const float* __restrict__ g0, const float* __restrict__ be0,
    const float* __restrict__ m0, const float* __restrict__ v0) {
    __shared__ float Wf[64 * 64];
    __shared__ float bf[64];

    const int b = blockIdx.y, tid = threadIdx.x;
    for (int i = tid; i < 64 * 64; i += 256) {
        int d = i & 63;
        Wf[i] = W0[(3 * 64) + i] * (g0[d] * rsqrtf(v0[d] + 1e-5f));
    }
    if (tid < 64) {
        float s = g0[tid] * rsqrtf(v0[tid] + 1e-5f);
        bf[tid] = (b0[tid] - m0[tid]) * s + be0[tid];
    }
    __syncthreads();

    const int row = blockIdx.x * 256 + tid;
    const float4* prow =
        reinterpret_cast<const float4*>(points + ((size_t)b * N_ + row) * D_);
    u64t acc[32];
    load64p(acc, bf);
#pragma unroll
    for (int j = 0; j < 16; j++) {
        float4 p = prow[j];
        acc_fma64p(acc, Wf + (4 * j + 0) * 64, pack2(p.x, p.x));
        acc_fma64p(acc, Wf + (4 * j + 1) * 64, pack2(p.y, p.y));
        acc_fma64p(acc, Wf + (4 * j + 2) * 64, pack2(p.z, p.z));
        acc_fma64p(acc, Wf + (4 * j + 3) * 64, pack2(p.w, p.w));
    }
    ulonglong2* out = reinterpret_cast<ulonglong2*>(
        g_P1 + ((size_t)b * N_ + row) * 64);
#pragma unroll
    for (int i = 0; i < 16; i++) {
        ulonglong2 t;
        t.x = acc[2 * i + 0];
        t.y = acc[2 * i + 1];
        out[i] = t;
    }
}

// Shared layout (floats):
//  0      xs[4096], 4096 ys, 8192 zs
//  12288  W1x[3*64] (xyz rows only)
//  12480  W2f[64*64]  16576 b2f[64]
//  16640  W3f[64*128] 24832 b3f[128]
//  24960  grp[8*32] (int)            -> total 25216 floats = 100864 bytes
#define SMEM_B_BYTES (25216 * 4)
#define SPB 114   // centroids per block (9 blocks * 114 >= 1024)

// ---------------------------------------------------------------------------
// Kernel 2 (R12-proven ~500us): ball query + P1 gather + xyz-only layer1 +
// MLP + max-pool. 256 threads, grid (9,16) = 144 CTAs single wave.
// ---------------------------------------------------------------------------
__global__ __launch_bounds__(256) void sa_kernel(
    const float* __restrict__ xyz,
    const float* __restrict__ W0,
    const float* __restrict__ g0, const float* __restrict__ v0,
    const float* __restrict__ W1, const float* __restrict__ b1,
    const float* __restrict__ g1, const float* __restrict__ be1,
    const float* __restrict__ m1, const float* __restrict__ v1,
    const float* __restrict__ W2, const float* __restrict__ b2,
    const float* __restrict__ g2, const float* __restrict__ be2,
    const float* __restrict__ m2, const float* __restrict__ v2,
    float* __restrict__ out_pts) {
    extern __shared__ float sm[];
    float* xs  = sm;
    float* ys  = sm + 4096;
    float* zs  = sm + 8192;
    float* W1x = sm + 12288;
    float* W2f = sm + 12480;
    float* b2f = sm + 16576;
    float* W3f = sm + 16640;
    float* b3f = sm + 24832;
    int* grpAll = (int*)(sm + 24960);

    const int b = blockIdx.y, tid = threadIdx.x;

    const float* xb = xyz + (size_t)b * N_ * 3;
    for (int i = tid; i < N_; i += 256) {
        xs[i] = xb[3 * i + 0];
        ys[i] = xb[3 * i + 1];
        zs[i] = xb[3 * i + 2];
    }
    // Fold BN: layer-1 xyz rows only (bias lives in P1)
    for (int i = tid; i < 3 * 64; i += 256) {
        int d = i & 63;
        W1x[i] = W0[i] * (g0[d] * rsqrtf(v0[d] + 1e-5f));
    }
    for (int i = tid; i < 64 * 64; i += 256) {
        int d = i & 63;
        W2f[i] = W1[i] * (g1[d] * rsqrtf(v1[d] + 1e-5f));
    }
    for (int i = tid; i < 64 * 128; i += 256) {
        int d = i & 127;
        W3f[i] = W2[i] * (g2[d] * rsqrtf(v2[d] + 1e-5f));
    }
    if (tid < 64) {
        float s = g1[tid] * rsqrtf(v1[tid] + 1e-5f);
        b2f[tid] = (b1[tid] - m1[tid]) * s + be1[tid];
    }
    if (tid < 128) {
        float s = g2[tid] * rsqrtf(v2[tid] + 1e-5f);
        b3f[tid] = (b2[tid] - m2[tid]) * s + be2[tid];
    }
    __syncthreads();

    const int w = tid >> 5, lane = tid & 31;
    int* grp = grpAll + w * K_;

    const int s0   = blockIdx.x * SPB;
    const int send = min(s0 + SPB, S_);

#pragma unroll 1
    for (int s = s0 + w; s < send; s += 8) {
        const int fidx = g_fps_idx[b * S_ + s];
        const float cx = xs[fidx], cy = ys[fidx], cz = zs[fidx];

        // ---- ball query: first-K in index order, ballot+popc, early exit ----
        grp[lane] = -1;
        __syncwarp();
        int cnt = 0;
        for (int base = 0; base < N_ && cnt < K_; base += 32) {
            const int j = base + lane;
            float dx = xs[j] - cx, dy = ys[j] - cy, dz = zs[j] - cz;
            float d2 = dx * dx + dy * dy + dz * dz;
            bool hit = d2 < 0.04f;   // f32(0.2**2), matches jax weak-typing
            unsigned mask = __ballot_sync(0xffffffffu, hit);
            if (hit) {
                int pos = cnt + __popc(mask & ((1u << lane) - 1u));
                if (pos < K_) grp[pos] = j;
            }
            cnt += __popc(mask);
        }
        __syncwarp();
        const int ni = grp[lane];
        const bool valid = ni >= 0;
        const int pidx = valid ? ni : (N_ - 1);          // torch -1 wrap for points
        const float in0 = (valid ? xs[ni] : 0.0f) - cx;  // grouped_xyz zeroed if pad
        const float in1 = (valid ? ys[ni] : 0.0f) - cy;
        const float in2 = (valid ? zs[ni] : 0.0f) - cz;
        const ulonglong2* p1row = reinterpret_cast<const ulonglong2*>(
            g_P1 + ((size_t)b * N_ + pidx) * 64);

        // ---- layer 1: acc = P1row (+ xyz-only inputs) ----
        u64t hp[32];
#pragma unroll
        for (int i = 0; i < 16; i++) {
            ulonglong2 t = p1row[i];
            hp[2 * i + 0] = t.x;
            hp[2 * i + 1] = t.y;
        }
        acc_fma64p(hp, W1x + 0 * 64, pack2(in0, in0));
        acc_fma64p(hp, W1x + 1 * 64, pack2(in1, in1));
        acc_fma64p(hp, W1x + 2 * 64, pack2(in2, in2));
        float h[64];
#pragma unroll
        for (int i = 0; i < 32; i++) {
            float a, c2;
            unpack2(hp[i], a, c2);
            h[2 * i + 0] = fmaxf(a, 0.0f);
            h[2 * i + 1] = fmaxf(c2, 0.0f);
        }

        // ---- layer 2: 64 -> 64 ----
        u64t h2p[32];
        load64p(h2p, b2f);
#pragma unroll
        for (int c = 0; c < 64; c++) acc_fma64p(h2p, W2f + c * 64, pack2(h[c], h[c]));
        float h2[64];
#pragma unroll
        for (int i = 0; i < 32; i++) {
            float a, c2;
            unpack2(h2p[i], a, c2);
            h2[2 * i + 0] = fmaxf(a, 0.0f);
            h2[2 * i + 1] = fmaxf(c2, 0.0f);
        }

        // ---- layer 3: 64 -> 128 in 4 chunks of 32, fused max over K ----
        float* outp = out_pts + ((size_t)(b * S_ + s)) * 128;
#pragma unroll 1
        for (int q = 0; q < 4; q++) {
            u64t vp[16];
            load32p(vp, b3f + q * 32);
#pragma unroll
            for (int c = 0; c < 64; c++)
                acc_fma32p(vp, W3f + c * 128 + q * 32, pack2(h2[c], h2[c]));
            float v[32];
#pragma unroll
            for (int i = 0; i < 16; i++) {
                float a, c2;
                unpack2(vp[i], a, c2);
                v[2 * i + 0] = fmaxf(a, 0.0f);
                v[2 * i + 1] = fmaxf(c2, 0.0f);
            }
            // transpose-reduce: lane l ends with max over lanes of channel q*32+l
#pragma unroll
            for (int hh = 16; hh >= 1; hh >>= 1) {
#pragma unroll
                for (int i = 0; i < hh; i++) {
                    float send2 = (lane & hh) ? v[i] : v[i + hh];
                    float recv = __shfl_xor_sync(0xffffffffu, send2, hh);
                    float keep = (lane & hh) ? v[i + hh] : v[i];
                    v[i] = fmaxf(keep, recv);
                }
            }
            outp[q * 32 + lane] = v[0];
        }
    }
}

// ---------------------------------------------------------------------------
extern "C" void kernel_launch(void* const* d_in, const int* in_sizes, int n_in,
                              void* d_out, int out_size) {
    const float* xyz    = (const float*)d_in[0];
    const float* points = (const float*)d_in[1];
    const float* W0  = (const float*)d_in[2];
    const float* b0  = (const float*)d_in[3];
    const float* g0  = (const float*)d_in[4];
    const float* be0 = (const float*)d_in[5];
    const float* m0  = (const float*)d_in[6];
    const float* v0  = (const float*)d_in[7];
    const float* W1  = (const float*)d_in[8];
    const float* b1  = (const float*)d_in[9];
    const float* g1  = (const float*)d_in[10];
    const float* be1 = (const float*)d_in[11];
    const float* m1  = (const float*)d_in[12];
    const float* v1  = (const float*)d_in[13];
    const float* W2  = (const float*)d_in[14];
    const float* b2  = (const float*)d_in[15];
    const float* g2  = (const float*)d_in[16];
    const float* be2 = (const float*)d_in[17];
    const float* m2  = (const float*)d_in[18];
    const float* v2  = (const float*)d_in[19];

    float* out_xyz = (float*)d_out;                       // (B,S,3)
    float* out_pts = (float*)d_out + (size_t)B_ * S_ * 3; // (B,S,128)

    cudaFuncSetAttribute(fps_kernel, cudaFuncAttributeMaxDynamicSharedMemorySize,
                         3 * N_ * 4);
    cudaFuncSetAttribute(sa_kernel, cudaFuncAttributeMaxDynamicSharedMemorySize,
                         SMEM_B_BYTES);

    fps_kernel<<<B_, 512, 3 * N_ * 4>>>(xyz, out_xyz);
    pre_kernel<<<dim3(16, B_), 256>>>(points, W0, b0, g0, be0, m0, v0);
    sa_kernel<<<dim3(9, B_), 256, SMEM_B_BYTES>>>(
        xyz,
        W0, g0, v0,
        W1, b1, g1, be1, m1, v1,
        W2, b2, g2, be2, m2, v2,
        out_pts);
}